// round 7
// baseline (speedup 1.0000x reference)
#include <cuda_runtime.h>
#include <cuda_bf16.h>
#include <math.h>
#include <stdint.h>

// Problem dims (fixed)
#define BATCH 4
#define SEQ   8192
#define DIM   512
#define HEADS 8
#define MROWS (BATCH*SEQ)

// scan chunking
#define CHUNK  128
#define NCHUNK (SEQ/CHUNK)

typedef __nv_bfloat16 bf16;

// ---------------------------------------------------------------------------
// device scratch (allocation-free rule -> __device__ globals)
// ---------------------------------------------------------------------------
__device__ float g_xp [(size_t)MROWS*DIM];     // GEMM1 output (fp32)
__device__ bf16  g_ah [(size_t)MROWS*DIM];     // x split hi
__device__ bf16  g_al [(size_t)MROWS*DIM];     // x split lo
__device__ bf16  g_yh [(size_t)MROWS*DIM];     // y split hi
__device__ bf16  g_yl [(size_t)MROWS*DIM];     // y split lo
__device__ bf16  g_w1h[DIM*DIM];
__device__ bf16  g_w1l[DIM*DIM];
__device__ bf16  g_w2h[DIM*DIM];
__device__ bf16  g_w2l[DIM*DIM];
__device__ float g_e  [(size_t)BATCH*NCHUNK*DIM];
__device__ float g_cin[(size_t)BATCH*NCHUNK*DIM];
__device__ float g_alpha[HEADS];

// ---------------------------------------------------------------------------
// helpers
// ---------------------------------------------------------------------------
__device__ __forceinline__ uint32_t s2u(const void* p) {
    uint32_t a;
    asm("{ .reg .u64 t; cvta.to.shared.u64 t, %1; cvt.u32.u64 %0, t; }"
        : "=r"(a) : "l"(p));
    return a;
}

__device__ __forceinline__ void ldsm4(uint32_t& r0, uint32_t& r1,
                                      uint32_t& r2, uint32_t& r3,
                                      uint32_t addr) {
    asm volatile("ldmatrix.sync.aligned.m8n8.x4.shared.b16 {%0,%1,%2,%3}, [%4];"
                 : "=r"(r0), "=r"(r1), "=r"(r2), "=r"(r3) : "r"(addr));
}

__device__ __forceinline__ void mma16816(float* c, const uint32_t* a,
                                         const uint32_t* b) {
    asm volatile(
        "mma.sync.aligned.m16n8k16.row.col.f32.bf16.bf16.f32 "
        "{%0,%1,%2,%3}, {%4,%5,%6,%7}, {%8,%9}, {%0,%1,%2,%3};"
        : "+f"(c[0]), "+f"(c[1]), "+f"(c[2]), "+f"(c[3])
        : "r"(a[0]), "r"(a[1]), "r"(a[2]), "r"(a[3]), "r"(b[0]), "r"(b[1]));
}

// ---------------------------------------------------------------------------
// alpha = sigmoid(alpha_param)
// ---------------------------------------------------------------------------
__global__ void alpha_kernel(const float* __restrict__ ap) {
    int h = threadIdx.x;
    if (h < HEADS) g_alpha[h] = 1.0f / (1.0f + expf(-ap[h]));
}

// ---------------------------------------------------------------------------
// fp32 -> bf16 hi/lo split (vectorized by 4)
// ---------------------------------------------------------------------------
__global__ void __launch_bounds__(256)
split_kernel(const float* __restrict__ src, bf16* __restrict__ hi,
             bf16* __restrict__ lo, int n4) {
    int i = blockIdx.x * blockDim.x + threadIdx.x;
    if (i >= n4) return;
    float4 v = ((const float4*)src)[i];
    float f[4] = {v.x, v.y, v.z, v.w};
    __nv_bfloat162 h[2], l[2];
#pragma unroll
    for (int k = 0; k < 2; k++) {
        bf16 h0 = __float2bfloat16(f[2*k]);
        bf16 h1 = __float2bfloat16(f[2*k+1]);
        bf16 l0 = __float2bfloat16(f[2*k]   - __bfloat162float(h0));
        bf16 l1 = __float2bfloat16(f[2*k+1] - __bfloat162float(h1));
        h[k].x = h0; h[k].y = h1;
        l[k].x = l0; l[k].y = l1;
    }
    ((__nv_bfloat162*)(hi + 4*(size_t)i))[0] = h[0];
    ((__nv_bfloat162*)(hi + 4*(size_t)i))[1] = h[1];
    ((__nv_bfloat162*)(lo + 4*(size_t)i))[0] = l[0];
    ((__nv_bfloat162*)(lo + 4*(size_t)i))[1] = l[1];
}

// ---------------------------------------------------------------------------
// bf16-split HMMA GEMM: C[m,n] = sum_k A[m,k]*B[n,k] + bias[n]
//   CTA 128x128, BK=64, 512 thr (16 warps 4x4), warp tile 32x32.
//   2-stage cp.async; xor swizzle; ldmatrix.x4; mma.m16n8k16; per-acc triples.
//   16 warps/SM (4 per SMSP) for latency hiding (R6 showed occ=12.5%, tensor 54%).
// ---------------------------------------------------------------------------
#define BM 128
#define BN 128
#define BK 64
#define KITERS (DIM/BK)     // 8
#define NTHREADS 512

#define AH_OFF 0
#define AL_OFF 16384
#define BH_OFF 32768
#define BL_OFF 49152
#define STAGE_BYTES 65536
#define SMEM_TOTAL (2*STAGE_BYTES)   // 128 KB

// swizzled byte offset inside a [128 rows x 128B] tile
#define TSWZ(row, c16) ((uint32_t)(row) * 128u + 16u * ((uint32_t)(c16) ^ ((uint32_t)(row) & 7u)))

__device__ __forceinline__ void load_stage(uint32_t sbase,
                                           const bf16* __restrict__ Ah,
                                           const bf16* __restrict__ Al,
                                           const bf16* __restrict__ Bh,
                                           const bf16* __restrict__ Bl,
                                           int m0, int n0, int k0, int tid) {
    // 4 matrices x 128 rows x 8 chunks(16B) = 4096 cp.async of 16B
#pragma unroll
    for (int q = 0; q < 8; q++) {
        int i = tid + q * NTHREADS;
        int mat = i >> 10;            // 0 Ah, 1 Al, 2 Bh, 3 Bl
        int j = i & 1023;
        int row = j >> 3;
        int c = j & 7;
        const bf16* src;
        uint32_t moff;
        if (mat == 0)      { src = Ah + (size_t)(m0 + row) * DIM; moff = AH_OFF; }
        else if (mat == 1) { src = Al + (size_t)(m0 + row) * DIM; moff = AL_OFF; }
        else if (mat == 2) { src = Bh + (size_t)(n0 + row) * DIM; moff = BH_OFF; }
        else               { src = Bl + (size_t)(n0 + row) * DIM; moff = BL_OFF; }
        src += k0 + c * 8;
        uint32_t dst = sbase + moff + TSWZ(row, c);
        asm volatile("cp.async.cg.shared.global [%0], [%1], 16;"
                     :: "r"(dst), "l"(src));
    }
}

__global__ void __launch_bounds__(NTHREADS, 1)
gemm_mma(const bf16* __restrict__ Ah, const bf16* __restrict__ Al,
         const bf16* __restrict__ Bh, const bf16* __restrict__ Bl,
         const float* __restrict__ bias, float* __restrict__ C) {
    extern __shared__ char smem[];
    uint32_t sb = s2u(smem);

    const int tid  = threadIdx.x;
    const int wid  = tid >> 5;
    const int lane = tid & 31;
    const int wm   = wid >> 2;           // 0..3 -> 32 rows each
    const int wn   = wid & 3;            // 0..3 -> 32 cols each
    const int m0   = blockIdx.y * BM;
    const int n0   = blockIdx.x * BN;

    float acc[2][4][4];
#pragma unroll
    for (int i = 0; i < 2; i++)
#pragma unroll
        for (int j = 0; j < 4; j++)
#pragma unroll
            for (int r = 0; r < 4; r++) acc[i][j][r] = 0.0f;

    // lane-invariant pieces of ldmatrix addresses
    const int arow = wm * 32 + (lane & 15);                      // + mt*16
    const int achk = lane >> 4;                                  // + 2*ks
    const int brow = wn * 32 + (lane & 7) + ((lane >> 4) << 3);  // + nt2*16
    const int bchk = (lane >> 3) & 1;                            // + 2*ks
    const uint32_t sxor = (uint32_t)(lane & 7);

    // prologue
    load_stage(sb, Ah, Al, Bh, Bl, m0, n0, 0, tid);
    asm volatile("cp.async.commit_group;" ::: "memory");

    for (int it = 0; it < KITERS; it++) {
        if (it + 1 < KITERS) {
            load_stage(sb + ((it + 1) & 1) * STAGE_BYTES,
                       Ah, Al, Bh, Bl, m0, n0, (it + 1) * BK, tid);
            asm volatile("cp.async.commit_group;" ::: "memory");
            asm volatile("cp.async.wait_group 1;" ::: "memory");
        } else {
            asm volatile("cp.async.wait_group 0;" ::: "memory");
        }
        __syncthreads();

        uint32_t st = sb + (it & 1) * STAGE_BYTES;
#pragma unroll
        for (int ks = 0; ks < BK / 16; ks++) {
            uint32_t ah[2][4], al[2][4];
#pragma unroll
            for (int mt = 0; mt < 2; mt++) {
                int row = arow + mt * 16;
                uint32_t co = (uint32_t)(2 * ks + achk) ^ sxor;
                uint32_t off = (uint32_t)row * 128u + co * 16u;
                ldsm4(ah[mt][0], ah[mt][1], ah[mt][2], ah[mt][3],
                      st + AH_OFF + off);
                ldsm4(al[mt][0], al[mt][1], al[mt][2], al[mt][3],
                      st + AL_OFF + off);
            }
            uint32_t bh[4][2], bl[4][2];
#pragma unroll
            for (int nt2 = 0; nt2 < 2; nt2++) {
                int row = brow + nt2 * 16;
                uint32_t co = (uint32_t)(2 * ks + bchk) ^ sxor;
                uint32_t off = (uint32_t)row * 128u + co * 16u;
                uint32_t r0, r1, r2, r3;
                ldsm4(r0, r1, r2, r3, st + BH_OFF + off);
                bh[nt2*2][0] = r0; bh[nt2*2][1] = r1;
                bh[nt2*2+1][0] = r2; bh[nt2*2+1][1] = r3;
                ldsm4(r0, r1, r2, r3, st + BL_OFF + off);
                bl[nt2*2][0] = r0; bl[nt2*2][1] = r1;
                bl[nt2*2+1][0] = r2; bl[nt2*2+1][1] = r3;
            }
            // per-acc triples (R3-proven ordering)
#pragma unroll
            for (int mt = 0; mt < 2; mt++)
#pragma unroll
                for (int nt = 0; nt < 4; nt++) {
                    mma16816(acc[mt][nt], ah[mt], bh[nt]);
                    mma16816(acc[mt][nt], al[mt], bh[nt]);
                    mma16816(acc[mt][nt], ah[mt], bl[nt]);
                }
        }
        __syncthreads();
    }

    // epilogue: acc -> C (+bias)
    const int erow = m0 + wm * 32 + (lane >> 2);
    const int ecol = n0 + wn * 32 + 2 * (lane & 3);
#pragma unroll
    for (int nt = 0; nt < 4; nt++) {
        int col = ecol + nt * 8;
        float b0 = bias[col], b1 = bias[col + 1];
#pragma unroll
        for (int mt = 0; mt < 2; mt++) {
            int row = erow + mt * 16;
            float2 v0 = make_float2(acc[mt][nt][0] + b0, acc[mt][nt][1] + b1);
            float2 v1 = make_float2(acc[mt][nt][2] + b0, acc[mt][nt][3] + b1);
            *(float2*)(C + (size_t)row * DIM + col)       = v0;
            *(float2*)(C + (size_t)(row + 8) * DIM + col) = v1;
        }
    }
}

// ---------------------------------------------------------------------------
// Chunked linear scan: y[t] = a*y[t-1] + alpha*(xp[t]-xp[t-1]),
// y[-1] = xp[-1] = init_state (channel index d = h*64 + dh)
// ---------------------------------------------------------------------------
__global__ void chunk_end_kernel(const float* __restrict__ init_state) {
    int d = threadIdx.x;
    int c = blockIdx.x, b = blockIdx.y;
    float alpha = g_alpha[d >> 6];
    float a = 1.0f - alpha;
    int t0 = c * CHUNK;
    const float* base = g_xp + ((size_t)b * SEQ + t0) * DIM + d;
    float prev = (t0 == 0) ? init_state[d] : *(base - DIM);
    float l = 0.0f;
#pragma unroll 4
    for (int t = 0; t < CHUNK; t++) {
        float cur = base[(size_t)t * DIM];
        l = a * l + alpha * (cur - prev);
        prev = cur;
    }
    g_e[((size_t)b * NCHUNK + c) * DIM + d] = l;
}

__global__ void __launch_bounds__(512)
carry_kernel(const float* __restrict__ init_state) {
    int d = threadIdx.x;
    int b = blockIdx.x;
    float a = 1.0f - g_alpha[d >> 6];
    float aN = powf(a, (float)CHUNK);
    float e[NCHUNK];
#pragma unroll
    for (int c = 0; c < NCHUNK; c++)
        e[c] = g_e[((size_t)b * NCHUNK + c) * DIM + d];
    float carry = init_state[d];
#pragma unroll
    for (int c = 0; c < NCHUNK; c++) {
        g_cin[((size_t)b * NCHUNK + c) * DIM + d] = carry;
        carry = fmaf(aN, carry, e[c]);
    }
}

__global__ void scan_kernel(const float* __restrict__ init_state) {
    int d = threadIdx.x;
    int c = blockIdx.x, b = blockIdx.y;
    float alpha = g_alpha[d >> 6];
    float a = 1.0f - alpha;
    int t0 = c * CHUNK;
    size_t off = ((size_t)b * SEQ + t0) * DIM + d;
    const float* base = g_xp + off;
    bf16* yh = g_yh + off;
    bf16* yl = g_yl + off;
    float prev = (t0 == 0) ? init_state[d] : *(base - DIM);
    float l = g_cin[((size_t)b * NCHUNK + c) * DIM + d];
#pragma unroll 4
    for (int t = 0; t < CHUNK; t++) {
        float cur = base[(size_t)t * DIM];
        l = a * l + alpha * (cur - prev);
        prev = cur;
        bf16 h = __float2bfloat16(l);
        yh[(size_t)t * DIM] = h;
        yl[(size_t)t * DIM] = __float2bfloat16(l - __bfloat162float(h));
    }
}

// ---------------------------------------------------------------------------
// launch
// ---------------------------------------------------------------------------
extern "C" void kernel_launch(void* const* d_in, const int* in_sizes, int n_in,
                              void* d_out, int out_size) {
    const float* x    = (const float*)d_in[0];
    const float* Win  = (const float*)d_in[1];
    const float* bin  = (const float*)d_in[2];
    const float* Wout = (const float*)d_in[3];
    const float* bout = (const float*)d_in[4];
    const float* init = (const float*)d_in[5];
    const float* ap   = (const float*)d_in[6];
    float* out = (float*)d_out;

    cudaFuncSetAttribute(gemm_mma, cudaFuncAttributeMaxDynamicSharedMemorySize,
                         SMEM_TOTAL);

    alpha_kernel<<<1, 32>>>(ap);

    bf16 *ah, *al, *w1h, *w1l, *w2h, *w2l, *yh, *yl;
    float *xp;
    cudaGetSymbolAddress((void**)&ah,  g_ah);
    cudaGetSymbolAddress((void**)&al,  g_al);
    cudaGetSymbolAddress((void**)&w1h, g_w1h);
    cudaGetSymbolAddress((void**)&w1l, g_w1l);
    cudaGetSymbolAddress((void**)&w2h, g_w2h);
    cudaGetSymbolAddress((void**)&w2l, g_w2l);
    cudaGetSymbolAddress((void**)&yh,  g_yh);
    cudaGetSymbolAddress((void**)&yl,  g_yl);
    cudaGetSymbolAddress((void**)&xp,  g_xp);

    int n4x = (MROWS * DIM) / 4;
    split_kernel<<<(n4x + 255) / 256, 256>>>(x, ah, al, n4x);
    int n4w = (DIM * DIM) / 4;
    split_kernel<<<(n4w + 255) / 256, 256>>>(Win,  w1h, w1l, n4w);
    split_kernel<<<(n4w + 255) / 256, 256>>>(Wout, w2h, w2l, n4w);

    dim3 ggrid(DIM / BN, MROWS / BM);
    gemm_mma<<<ggrid, NTHREADS, SMEM_TOTAL>>>(ah, al, w1h, w1l, bin, xp);

    chunk_end_kernel<<<dim3(NCHUNK, BATCH), DIM>>>(init);
    carry_kernel<<<BATCH, DIM>>>(init);
    scan_kernel<<<dim3(NCHUNK, BATCH), DIM>>>(init);

    gemm_mma<<<ggrid, NTHREADS, SMEM_TOTAL>>>(yh, yl, w2h, w2l, bout, out);
}

// round 8
// speedup vs baseline: 1.2837x; 1.2837x over previous
#include <cuda_runtime.h>
#include <cuda_fp16.h>
#include <math.h>
#include <stdint.h>

// Problem dims (fixed)
#define BATCH 4
#define SEQ   8192
#define DIM   512
#define HEADS 8
#define MROWS (BATCH*SEQ)

// scan chunking
#define CHUNK  128
#define NCHUNK (SEQ/CHUNK)

// ---------------------------------------------------------------------------
// device scratch (allocation-free rule -> __device__ globals)
// ---------------------------------------------------------------------------
__device__ float  g_xp [(size_t)MROWS*DIM];     // GEMM1 output (fp32)
__device__ __half g_xh [(size_t)MROWS*DIM];     // x as fp16
__device__ __half g_yh [(size_t)MROWS*DIM];     // y as fp16
__device__ __half g_w1h[DIM*DIM];               // W_in  hi
__device__ __half g_w1l[DIM*DIM];               // W_in  lo
__device__ __half g_w2h[DIM*DIM];               // W_out hi
__device__ __half g_w2l[DIM*DIM];               // W_out lo
__device__ float  g_e  [(size_t)BATCH*NCHUNK*DIM];
__device__ float  g_cin[(size_t)BATCH*NCHUNK*DIM];
__device__ float  g_alpha[HEADS];

// ---------------------------------------------------------------------------
// helpers
// ---------------------------------------------------------------------------
__device__ __forceinline__ uint32_t s2u(const void* p) {
    uint32_t a;
    asm("{ .reg .u64 t; cvta.to.shared.u64 t, %1; cvt.u32.u64 %0, t; }"
        : "=r"(a) : "l"(p));
    return a;
}

__device__ __forceinline__ void ldsm4(uint32_t& r0, uint32_t& r1,
                                      uint32_t& r2, uint32_t& r3,
                                      uint32_t addr) {
    asm volatile("ldmatrix.sync.aligned.m8n8.x4.shared.b16 {%0,%1,%2,%3}, [%4];"
                 : "=r"(r0), "=r"(r1), "=r"(r2), "=r"(r3) : "r"(addr));
}

__device__ __forceinline__ void mma16816(float* c, const uint32_t* a,
                                         const uint32_t* b) {
    asm volatile(
        "mma.sync.aligned.m16n8k16.row.col.f32.f16.f16.f32 "
        "{%0,%1,%2,%3}, {%4,%5,%6,%7}, {%8,%9}, {%0,%1,%2,%3};"
        : "+f"(c[0]), "+f"(c[1]), "+f"(c[2]), "+f"(c[3])
        : "r"(a[0]), "r"(a[1]), "r"(a[2]), "r"(a[3]), "r"(b[0]), "r"(b[1]));
}

// ---------------------------------------------------------------------------
// alpha = sigmoid(alpha_param)
// ---------------------------------------------------------------------------
__global__ void alpha_kernel(const float* __restrict__ ap) {
    int h = threadIdx.x;
    if (h < HEADS) g_alpha[h] = 1.0f / (1.0f + expf(-ap[h]));
}

// ---------------------------------------------------------------------------
// weight fp32 -> fp16 hi/lo split
// ---------------------------------------------------------------------------
__global__ void __launch_bounds__(256)
splitw_kernel(const float* __restrict__ src, __half* __restrict__ hi,
              __half* __restrict__ lo, int n4) {
    int i = blockIdx.x * blockDim.x + threadIdx.x;
    if (i >= n4) return;
    float4 v = ((const float4*)src)[i];
    float f[4] = {v.x, v.y, v.z, v.w};
    __half2 h[2], l[2];
#pragma unroll
    for (int k = 0; k < 2; k++) {
        __half h0 = __float2half_rn(f[2*k]);
        __half h1 = __float2half_rn(f[2*k+1]);
        __half l0 = __float2half_rn(f[2*k]   - __half2float(h0));
        __half l1 = __float2half_rn(f[2*k+1] - __half2float(h1));
        h[k] = __halves2half2(h0, h1);
        l[k] = __halves2half2(l0, l1);
    }
    ((__half2*)(hi + 4*(size_t)i))[0] = h[0];
    ((__half2*)(hi + 4*(size_t)i))[1] = h[1];
    ((__half2*)(lo + 4*(size_t)i))[0] = l[0];
    ((__half2*)(lo + 4*(size_t)i))[1] = l[1];
}

// ---------------------------------------------------------------------------
// activation fp32 -> fp16
// ---------------------------------------------------------------------------
__global__ void __launch_bounds__(256)
convx_kernel(const float* __restrict__ src, __half* __restrict__ dst, int n4) {
    int i = blockIdx.x * blockDim.x + threadIdx.x;
    if (i >= n4) return;
    float4 v = ((const float4*)src)[i];
    __half2 h0 = __halves2half2(__float2half_rn(v.x), __float2half_rn(v.y));
    __half2 h1 = __halves2half2(__float2half_rn(v.z), __float2half_rn(v.w));
    ((__half2*)(dst + 4*(size_t)i))[0] = h0;
    ((__half2*)(dst + 4*(size_t)i))[1] = h1;
}

// ---------------------------------------------------------------------------
// fp16 2-term HMMA GEMM: C[m,n] = sum_k A[m,k]*(Bh+Bl)[n,k] + bias[n]
//   A fp16 [MROWS,DIM]; B = Bh+Bl fp16 [DIM,DIM]; C fp32.
//   CTA 128x128, BK=64, 256 thr (8 warps 2x4), warp tile 64x32.
//   2-stage cp.async; xor swizzle; ldmatrix.x4; mma.m16n8k16.f16.
// ---------------------------------------------------------------------------
#define BM 128
#define BN 128
#define BK 64
#define KITERS (DIM/BK)     // 8

#define XA_OFF 0
#define BH_OFF 16384
#define BL_OFF 32768
#define STAGE_BYTES 49152
#define SMEM_TOTAL (2*STAGE_BYTES)   // 96 KB

// swizzled byte offset inside a [128 rows x 128B] tile
#define TSWZ(row, c16) ((uint32_t)(row) * 128u + 16u * ((uint32_t)(c16) ^ ((uint32_t)(row) & 7u)))

__device__ __forceinline__ void load_stage(uint32_t sbase,
                                           const __half* __restrict__ A,
                                           const __half* __restrict__ Bh,
                                           const __half* __restrict__ Bl,
                                           int m0, int n0, int k0, int tid) {
    // 3 matrices x 128 rows x 8 chunks(16B) = 3072 cp.async of 16B
#pragma unroll
    for (int q = 0; q < 12; q++) {
        int i = tid + q * 256;
        int mat = i >> 10;            // 0 A, 1 Bh, 2 Bl
        int j = i & 1023;
        int row = j >> 3;
        int c = j & 7;
        const __half* src;
        uint32_t moff;
        if (mat == 0)      { src = A  + (size_t)(m0 + row) * DIM; moff = XA_OFF; }
        else if (mat == 1) { src = Bh + (size_t)(n0 + row) * DIM; moff = BH_OFF; }
        else               { src = Bl + (size_t)(n0 + row) * DIM; moff = BL_OFF; }
        src += k0 + c * 8;
        uint32_t dst = sbase + moff + TSWZ(row, c);
        asm volatile("cp.async.cg.shared.global [%0], [%1], 16;"
                     :: "r"(dst), "l"(src));
    }
}

__global__ void __launch_bounds__(256, 1)
gemm_mma(const __half* __restrict__ A,
         const __half* __restrict__ Bh, const __half* __restrict__ Bl,
         const float* __restrict__ bias, float* __restrict__ C) {
    extern __shared__ char smem[];
    uint32_t sb = s2u(smem);

    const int tid  = threadIdx.x;
    const int wid  = tid >> 5;
    const int lane = tid & 31;
    const int wm   = wid >> 2;           // 0..1 -> 64 rows each
    const int wn   = wid & 3;            // 0..3 -> 32 cols each
    const int m0   = blockIdx.y * BM;
    const int n0   = blockIdx.x * BN;

    float acc[4][4][4];
#pragma unroll
    for (int i = 0; i < 4; i++)
#pragma unroll
        for (int j = 0; j < 4; j++)
#pragma unroll
            for (int r = 0; r < 4; r++) acc[i][j][r] = 0.0f;

    // lane-invariant pieces of ldmatrix addresses
    const int arow = wm * 64 + (lane & 15);           // + mt*16
    const int achk = lane >> 4;                       // + 2*ks
    const int brow = wn * 32 + (lane & 7) + ((lane >> 4) << 3);  // + nt2*16
    const int bchk = (lane >> 3) & 1;                 // + 2*ks
    const uint32_t sxor = (uint32_t)(lane & 7);

    // prologue
    load_stage(sb, A, Bh, Bl, m0, n0, 0, tid);
    asm volatile("cp.async.commit_group;" ::: "memory");

    for (int it = 0; it < KITERS; it++) {
        if (it + 1 < KITERS) {
            load_stage(sb + ((it + 1) & 1) * STAGE_BYTES,
                       A, Bh, Bl, m0, n0, (it + 1) * BK, tid);
            asm volatile("cp.async.commit_group;" ::: "memory");
            asm volatile("cp.async.wait_group 1;" ::: "memory");
        } else {
            asm volatile("cp.async.wait_group 0;" ::: "memory");
        }
        __syncthreads();

        uint32_t st = sb + (it & 1) * STAGE_BYTES;
#pragma unroll
        for (int ks = 0; ks < BK / 16; ks++) {
            uint32_t av[4][4];
#pragma unroll
            for (int mt = 0; mt < 4; mt++) {
                int row = arow + mt * 16;
                uint32_t co = (uint32_t)(2 * ks + achk) ^ sxor;
                uint32_t off = (uint32_t)row * 128u + co * 16u;
                ldsm4(av[mt][0], av[mt][1], av[mt][2], av[mt][3],
                      st + XA_OFF + off);
            }
            uint32_t bh[4][2], bl[4][2];
#pragma unroll
            for (int nt2 = 0; nt2 < 2; nt2++) {
                int row = brow + nt2 * 16;
                uint32_t co = (uint32_t)(2 * ks + bchk) ^ sxor;
                uint32_t off = (uint32_t)row * 128u + co * 16u;
                uint32_t r0, r1, r2, r3;
                ldsm4(r0, r1, r2, r3, st + BH_OFF + off);
                bh[nt2*2][0] = r0; bh[nt2*2][1] = r1;
                bh[nt2*2+1][0] = r2; bh[nt2*2+1][1] = r3;
                ldsm4(r0, r1, r2, r3, st + BL_OFF + off);
                bl[nt2*2][0] = r0; bl[nt2*2][1] = r1;
                bl[nt2*2+1][0] = r2; bl[nt2*2+1][1] = r3;
            }
#pragma unroll
            for (int mt = 0; mt < 4; mt++)
#pragma unroll
                for (int nt = 0; nt < 4; nt++) {
                    mma16816(acc[mt][nt], av[mt], bh[nt]);
                    mma16816(acc[mt][nt], av[mt], bl[nt]);
                }
        }
        __syncthreads();
    }

    // epilogue: acc -> C (+bias)
    const int erow = m0 + wm * 64 + (lane >> 2);
    const int ecol = n0 + wn * 32 + 2 * (lane & 3);
#pragma unroll
    for (int nt = 0; nt < 4; nt++) {
        int col = ecol + nt * 8;
        float b0 = bias[col], b1 = bias[col + 1];
#pragma unroll
        for (int mt = 0; mt < 4; mt++) {
            int row = erow + mt * 16;
            float2 v0 = make_float2(acc[mt][nt][0] + b0, acc[mt][nt][1] + b1);
            float2 v1 = make_float2(acc[mt][nt][2] + b0, acc[mt][nt][3] + b1);
            *(float2*)(C + (size_t)row * DIM + col)       = v0;
            *(float2*)(C + (size_t)(row + 8) * DIM + col) = v1;
        }
    }
}

// ---------------------------------------------------------------------------
// Chunked linear scan: y[t] = a*y[t-1] + alpha*(xp[t]-xp[t-1]),
// y[-1] = xp[-1] = init_state (channel index d = h*64 + dh)
// ---------------------------------------------------------------------------
__global__ void chunk_end_kernel(const float* __restrict__ init_state) {
    int d = threadIdx.x;
    int c = blockIdx.x, b = blockIdx.y;
    float alpha = g_alpha[d >> 6];
    float a = 1.0f - alpha;
    int t0 = c * CHUNK;
    const float* base = g_xp + ((size_t)b * SEQ + t0) * DIM + d;
    float prev = (t0 == 0) ? init_state[d] : *(base - DIM);
    float l = 0.0f;
#pragma unroll 4
    for (int t = 0; t < CHUNK; t++) {
        float cur = base[(size_t)t * DIM];
        l = a * l + alpha * (cur - prev);
        prev = cur;
    }
    g_e[((size_t)b * NCHUNK + c) * DIM + d] = l;
}

__global__ void __launch_bounds__(512)
carry_kernel(const float* __restrict__ init_state) {
    int d = threadIdx.x;
    int b = blockIdx.x;
    float a = 1.0f - g_alpha[d >> 6];
    float aN = powf(a, (float)CHUNK);
    float e[NCHUNK];
#pragma unroll
    for (int c = 0; c < NCHUNK; c++)
        e[c] = g_e[((size_t)b * NCHUNK + c) * DIM + d];
    float carry = init_state[d];
#pragma unroll
    for (int c = 0; c < NCHUNK; c++) {
        g_cin[((size_t)b * NCHUNK + c) * DIM + d] = carry;
        carry = fmaf(aN, carry, e[c]);
    }
}

__global__ void scan_kernel(const float* __restrict__ init_state) {
    int d = threadIdx.x;
    int c = blockIdx.x, b = blockIdx.y;
    float alpha = g_alpha[d >> 6];
    float a = 1.0f - alpha;
    int t0 = c * CHUNK;
    size_t off = ((size_t)b * SEQ + t0) * DIM + d;
    const float* base = g_xp + off;
    __half* y = g_yh + off;
    float prev = (t0 == 0) ? init_state[d] : *(base - DIM);
    float l = g_cin[((size_t)b * NCHUNK + c) * DIM + d];
#pragma unroll 4
    for (int t = 0; t < CHUNK; t++) {
        float cur = base[(size_t)t * DIM];
        l = a * l + alpha * (cur - prev);
        prev = cur;
        y[(size_t)t * DIM] = __float2half_rn(l);
    }
}

// ---------------------------------------------------------------------------
// launch
// ---------------------------------------------------------------------------
extern "C" void kernel_launch(void* const* d_in, const int* in_sizes, int n_in,
                              void* d_out, int out_size) {
    const float* x    = (const float*)d_in[0];
    const float* Win  = (const float*)d_in[1];
    const float* bin  = (const float*)d_in[2];
    const float* Wout = (const float*)d_in[3];
    const float* bout = (const float*)d_in[4];
    const float* init = (const float*)d_in[5];
    const float* ap   = (const float*)d_in[6];
    float* out = (float*)d_out;

    cudaFuncSetAttribute(gemm_mma, cudaFuncAttributeMaxDynamicSharedMemorySize,
                         SMEM_TOTAL);

    alpha_kernel<<<1, 32>>>(ap);

    __half *xh, *w1h, *w1l, *w2h, *w2l, *yh;
    float *xp;
    cudaGetSymbolAddress((void**)&xh,  g_xh);
    cudaGetSymbolAddress((void**)&w1h, g_w1h);
    cudaGetSymbolAddress((void**)&w1l, g_w1l);
    cudaGetSymbolAddress((void**)&w2h, g_w2h);
    cudaGetSymbolAddress((void**)&w2l, g_w2l);
    cudaGetSymbolAddress((void**)&yh,  g_yh);
    cudaGetSymbolAddress((void**)&xp,  g_xp);

    int n4x = (MROWS * DIM) / 4;
    convx_kernel<<<(n4x + 255) / 256, 256>>>(x, xh, n4x);
    int n4w = (DIM * DIM) / 4;
    splitw_kernel<<<(n4w + 255) / 256, 256>>>(Win,  w1h, w1l, n4w);
    splitw_kernel<<<(n4w + 255) / 256, 256>>>(Wout, w2h, w2l, n4w);

    dim3 ggrid(DIM / BN, MROWS / BM);
    gemm_mma<<<ggrid, 256, SMEM_TOTAL>>>(xh, w1h, w1l, bin, xp);

    chunk_end_kernel<<<dim3(NCHUNK, BATCH), DIM>>>(init);
    carry_kernel<<<BATCH, DIM>>>(init);
    scan_kernel<<<dim3(NCHUNK, BATCH), DIM>>>(init);

    gemm_mma<<<ggrid, 256, SMEM_TOTAL>>>(yh, w2h, w2l, bout, out);
}

// round 9
// speedup vs baseline: 1.8092x; 1.4093x over previous
#include <cuda_runtime.h>
#include <cuda_fp16.h>
#include <math.h>
#include <stdint.h>

// Problem dims (fixed)
#define BATCH 4
#define SEQ   8192
#define DIM   512
#define HEADS 8
#define MROWS (BATCH*SEQ)

// scan chunking
#define CHUNK  128
#define NCHUNK (SEQ/CHUNK)

// ---------------------------------------------------------------------------
// device scratch (allocation-free rule -> __device__ globals)
// ---------------------------------------------------------------------------
__device__ float  g_xp [(size_t)MROWS*DIM];     // GEMM1 output (fp32)
__device__ __half g_xh [(size_t)MROWS*DIM];     // x as fp16
__device__ __half g_yh [(size_t)MROWS*DIM];     // y as fp16
__device__ __half g_w1 [DIM*DIM];               // W_in  fp16
__device__ __half g_w2 [DIM*DIM];               // W_out fp16
__device__ float  g_e  [(size_t)BATCH*NCHUNK*DIM];
__device__ float  g_cin[(size_t)BATCH*NCHUNK*DIM];
__device__ float  g_alpha[HEADS];

// ---------------------------------------------------------------------------
// helpers
// ---------------------------------------------------------------------------
__device__ __forceinline__ uint32_t s2u(const void* p) {
    uint32_t a;
    asm("{ .reg .u64 t; cvta.to.shared.u64 t, %1; cvt.u32.u64 %0, t; }"
        : "=r"(a) : "l"(p));
    return a;
}

__device__ __forceinline__ void ldsm4(uint32_t& r0, uint32_t& r1,
                                      uint32_t& r2, uint32_t& r3,
                                      uint32_t addr) {
    asm volatile("ldmatrix.sync.aligned.m8n8.x4.shared.b16 {%0,%1,%2,%3}, [%4];"
                 : "=r"(r0), "=r"(r1), "=r"(r2), "=r"(r3) : "r"(addr));
}

__device__ __forceinline__ void mma16816(float* c, const uint32_t* a,
                                         const uint32_t* b) {
    asm volatile(
        "mma.sync.aligned.m16n8k16.row.col.f32.f16.f16.f32 "
        "{%0,%1,%2,%3}, {%4,%5,%6,%7}, {%8,%9}, {%0,%1,%2,%3};"
        : "+f"(c[0]), "+f"(c[1]), "+f"(c[2]), "+f"(c[3])
        : "r"(a[0]), "r"(a[1]), "r"(a[2]), "r"(a[3]), "r"(b[0]), "r"(b[1]));
}

// ---------------------------------------------------------------------------
// alpha = sigmoid(alpha_param)
// ---------------------------------------------------------------------------
__global__ void alpha_kernel(const float* __restrict__ ap) {
    int h = threadIdx.x;
    if (h < HEADS) g_alpha[h] = 1.0f / (1.0f + expf(-ap[h]));
}

// ---------------------------------------------------------------------------
// fp32 -> fp16 convert (vectorized by 4)
// ---------------------------------------------------------------------------
__global__ void __launch_bounds__(256)
convx_kernel(const float* __restrict__ src, __half* __restrict__ dst, int n4) {
    int i = blockIdx.x * blockDim.x + threadIdx.x;
    if (i >= n4) return;
    float4 v = ((const float4*)src)[i];
    __half2 h0 = __halves2half2(__float2half_rn(v.x), __float2half_rn(v.y));
    __half2 h1 = __halves2half2(__float2half_rn(v.z), __float2half_rn(v.w));
    ((__half2*)(dst + 4*(size_t)i))[0] = h0;
    ((__half2*)(dst + 4*(size_t)i))[1] = h1;
}

// ---------------------------------------------------------------------------
// fp16 HMMA GEMM: C[m,n] = sum_k A[m,k]*B[n,k] + bias[n]
//   A fp16 [MROWS,DIM]; B fp16 [DIM,DIM]; C fp32.
//   CTA 128x128, BK=64, 256 thr (8 warps 2x4), warp tile 64x32.
//   2-stage cp.async; xor swizzle; ldmatrix.x4; mma.m16n8k16.f16.
//   2 CTAs/SM (64KB smem, ~120 regs) for latency hiding.
// ---------------------------------------------------------------------------
#define BM 128
#define BN 128
#define BK 64
#define KITERS (DIM/BK)     // 8

#define XA_OFF 0
#define BB_OFF 16384
#define STAGE_BYTES 32768
#define SMEM_TOTAL (2*STAGE_BYTES)   // 64 KB

// swizzled byte offset inside a [128 rows x 128B] tile
#define TSWZ(row, c16) ((uint32_t)(row) * 128u + 16u * ((uint32_t)(c16) ^ ((uint32_t)(row) & 7u)))

__device__ __forceinline__ void load_stage(uint32_t sbase,
                                           const __half* __restrict__ A,
                                           const __half* __restrict__ B,
                                           int m0, int n0, int k0, int tid) {
    // 2 matrices x 128 rows x 8 chunks(16B) = 2048 cp.async of 16B
#pragma unroll
    for (int q = 0; q < 8; q++) {
        int i = tid + q * 256;
        int mat = i >> 10;            // 0 A, 1 B
        int j = i & 1023;
        int row = j >> 3;
        int c = j & 7;
        const __half* src = (mat ? B + (size_t)(n0 + row) * DIM
                                 : A + (size_t)(m0 + row) * DIM) + k0 + c * 8;
        uint32_t dst = sbase + (mat ? BB_OFF : XA_OFF) + TSWZ(row, c);
        asm volatile("cp.async.cg.shared.global [%0], [%1], 16;"
                     :: "r"(dst), "l"(src));
    }
}

__global__ void __launch_bounds__(256, 2)
gemm_mma(const __half* __restrict__ A, const __half* __restrict__ B,
         const float* __restrict__ bias, float* __restrict__ C) {
    extern __shared__ char smem[];
    uint32_t sb = s2u(smem);

    const int tid  = threadIdx.x;
    const int wid  = tid >> 5;
    const int lane = tid & 31;
    const int wm   = wid >> 2;           // 0..1 -> 64 rows each
    const int wn   = wid & 3;            // 0..3 -> 32 cols each
    const int m0   = blockIdx.y * BM;
    const int n0   = blockIdx.x * BN;

    float acc[4][4][4];
#pragma unroll
    for (int i = 0; i < 4; i++)
#pragma unroll
        for (int j = 0; j < 4; j++)
#pragma unroll
            for (int r = 0; r < 4; r++) acc[i][j][r] = 0.0f;

    // lane-invariant pieces of ldmatrix addresses
    const int arow = wm * 64 + (lane & 15);           // + mt*16
    const int achk = lane >> 4;                       // + 2*ks
    const int brow = wn * 32 + (lane & 7) + ((lane >> 4) << 3);  // + nt2*16
    const int bchk = (lane >> 3) & 1;                 // + 2*ks
    const uint32_t sxor = (uint32_t)(lane & 7);

    // prologue
    load_stage(sb, A, B, m0, n0, 0, tid);
    asm volatile("cp.async.commit_group;" ::: "memory");

    for (int it = 0; it < KITERS; it++) {
        if (it + 1 < KITERS) {
            load_stage(sb + ((it + 1) & 1) * STAGE_BYTES,
                       A, B, m0, n0, (it + 1) * BK, tid);
            asm volatile("cp.async.commit_group;" ::: "memory");
            asm volatile("cp.async.wait_group 1;" ::: "memory");
        } else {
            asm volatile("cp.async.wait_group 0;" ::: "memory");
        }
        __syncthreads();

        uint32_t st = sb + (it & 1) * STAGE_BYTES;
#pragma unroll
        for (int ks = 0; ks < BK / 16; ks++) {
            uint32_t av[4][4];
#pragma unroll
            for (int mt = 0; mt < 4; mt++) {
                int row = arow + mt * 16;
                uint32_t co = (uint32_t)(2 * ks + achk) ^ sxor;
                uint32_t off = (uint32_t)row * 128u + co * 16u;
                ldsm4(av[mt][0], av[mt][1], av[mt][2], av[mt][3],
                      st + XA_OFF + off);
            }
            uint32_t bv[4][2];
#pragma unroll
            for (int nt2 = 0; nt2 < 2; nt2++) {
                int row = brow + nt2 * 16;
                uint32_t co = (uint32_t)(2 * ks + bchk) ^ sxor;
                uint32_t off = (uint32_t)row * 128u + co * 16u;
                uint32_t r0, r1, r2, r3;
                ldsm4(r0, r1, r2, r3, st + BB_OFF + off);
                bv[nt2*2][0] = r0; bv[nt2*2][1] = r1;
                bv[nt2*2+1][0] = r2; bv[nt2*2+1][1] = r3;
            }
#pragma unroll
            for (int mt = 0; mt < 4; mt++)
#pragma unroll
                for (int nt = 0; nt < 4; nt++)
                    mma16816(acc[mt][nt], av[mt], bv[nt]);
        }
        __syncthreads();
    }

    // epilogue: acc -> C (+bias)
    const int erow = m0 + wm * 64 + (lane >> 2);
    const int ecol = n0 + wn * 32 + 2 * (lane & 3);
#pragma unroll
    for (int nt = 0; nt < 4; nt++) {
        int col = ecol + nt * 8;
        float b0 = bias[col], b1 = bias[col + 1];
#pragma unroll
        for (int mt = 0; mt < 4; mt++) {
            int row = erow + mt * 16;
            float2 v0 = make_float2(acc[mt][nt][0] + b0, acc[mt][nt][1] + b1);
            float2 v1 = make_float2(acc[mt][nt][2] + b0, acc[mt][nt][3] + b1);
            *(float2*)(C + (size_t)row * DIM + col)       = v0;
            *(float2*)(C + (size_t)(row + 8) * DIM + col) = v1;
        }
    }
}

// ---------------------------------------------------------------------------
// Chunked linear scan: y[t] = a*y[t-1] + alpha*(xp[t]-xp[t-1]),
// y[-1] = xp[-1] = init_state (channel index d = h*64 + dh)
// ---------------------------------------------------------------------------
__global__ void chunk_end_kernel(const float* __restrict__ init_state) {
    int d = threadIdx.x;
    int c = blockIdx.x, b = blockIdx.y;
    float alpha = g_alpha[d >> 6];
    float a = 1.0f - alpha;
    int t0 = c * CHUNK;
    const float* base = g_xp + ((size_t)b * SEQ + t0) * DIM + d;
    float prev = (t0 == 0) ? init_state[d] : *(base - DIM);
    float l = 0.0f;
#pragma unroll 4
    for (int t = 0; t < CHUNK; t++) {
        float cur = base[(size_t)t * DIM];
        l = a * l + alpha * (cur - prev);
        prev = cur;
    }
    g_e[((size_t)b * NCHUNK + c) * DIM + d] = l;
}

__global__ void __launch_bounds__(512)
carry_kernel(const float* __restrict__ init_state) {
    int d = threadIdx.x;
    int b = blockIdx.x;
    float a = 1.0f - g_alpha[d >> 6];
    float aN = powf(a, (float)CHUNK);
    float e[NCHUNK];
#pragma unroll
    for (int c = 0; c < NCHUNK; c++)
        e[c] = g_e[((size_t)b * NCHUNK + c) * DIM + d];
    float carry = init_state[d];
#pragma unroll
    for (int c = 0; c < NCHUNK; c++) {
        g_cin[((size_t)b * NCHUNK + c) * DIM + d] = carry;
        carry = fmaf(aN, carry, e[c]);
    }
}

__global__ void scan_kernel(const float* __restrict__ init_state) {
    int d = threadIdx.x;
    int c = blockIdx.x, b = blockIdx.y;
    float alpha = g_alpha[d >> 6];
    float a = 1.0f - alpha;
    int t0 = c * CHUNK;
    size_t off = ((size_t)b * SEQ + t0) * DIM + d;
    const float* base = g_xp + off;
    __half* y = g_yh + off;
    float prev = (t0 == 0) ? init_state[d] : *(base - DIM);
    float l = g_cin[((size_t)b * NCHUNK + c) * DIM + d];
#pragma unroll 4
    for (int t = 0; t < CHUNK; t++) {
        float cur = base[(size_t)t * DIM];
        l = a * l + alpha * (cur - prev);
        prev = cur;
        y[(size_t)t * DIM] = __float2half_rn(l);
    }
}

// ---------------------------------------------------------------------------
// launch
// ---------------------------------------------------------------------------
extern "C" void kernel_launch(void* const* d_in, const int* in_sizes, int n_in,
                              void* d_out, int out_size) {
    const float* x    = (const float*)d_in[0];
    const float* Win  = (const float*)d_in[1];
    const float* bin  = (const float*)d_in[2];
    const float* Wout = (const float*)d_in[3];
    const float* bout = (const float*)d_in[4];
    const float* init = (const float*)d_in[5];
    const float* ap   = (const float*)d_in[6];
    float* out = (float*)d_out;

    cudaFuncSetAttribute(gemm_mma, cudaFuncAttributeMaxDynamicSharedMemorySize,
                         SMEM_TOTAL);

    alpha_kernel<<<1, 32>>>(ap);

    __half *xh, *w1, *w2, *yh;
    float *xp;
    cudaGetSymbolAddress((void**)&xh, g_xh);
    cudaGetSymbolAddress((void**)&w1, g_w1);
    cudaGetSymbolAddress((void**)&w2, g_w2);
    cudaGetSymbolAddress((void**)&yh, g_yh);
    cudaGetSymbolAddress((void**)&xp, g_xp);

    int n4x = (MROWS * DIM) / 4;
    convx_kernel<<<(n4x + 255) / 256, 256>>>(x, xh, n4x);
    int n4w = (DIM * DIM) / 4;
    convx_kernel<<<(n4w + 255) / 256, 256>>>(Win,  w1, n4w);
    convx_kernel<<<(n4w + 255) / 256, 256>>>(Wout, w2, n4w);

    dim3 ggrid(DIM / BN, MROWS / BM);
    gemm_mma<<<ggrid, 256, SMEM_TOTAL>>>(xh, w1, bin, xp);

    chunk_end_kernel<<<dim3(NCHUNK, BATCH), DIM>>>(init);
    carry_kernel<<<BATCH, DIM>>>(init);
    scan_kernel<<<dim3(NCHUNK, BATCH), DIM>>>(init);

    gemm_mma<<<ggrid, 256, SMEM_TOTAL>>>(yh, w2, bout, out);
}